// round 11
// baseline (speedup 1.0000x reference)
#include <cuda_runtime.h>
#include <cuda_fp16.h>
#include <cstdint>
#include <cstddef>

#define GH 1024
#define GW 1024
#define GC 32
#define GHW (GH * GW)

// 64 MB transposed fp16 params: [HW, C], 64B per cell.
__device__ __half g_params_h[(size_t)GHW * GC];

__device__ __forceinline__ uint64_t evict_last_policy() {
    uint64_t p;
    asm("createpolicy.fractional.L2::evict_last.b64 %0, 1.0;" : "=l"(p));
    return p;
}

__device__ __forceinline__ void st16_evict_last(uint4* ptr, uint4 v, uint64_t pol) {
    asm volatile("st.global.L2::cache_hint.v4.u32 [%0], {%1,%2,%3,%4}, %5;"
                 :: "l"(ptr), "r"(v.x), "r"(v.y), "r"(v.z), "r"(v.w), "l"(pol)
                 : "memory");
}

// ---------------------------------------------------------------------------
// Kernel 1: transpose + convert, no smem. One thread = one point.
// Params enter L2 with evict_last priority (survive the output stream,
// suppress writeback during the gather).
// ---------------------------------------------------------------------------
__global__ void transpose_kernel(const float* __restrict__ in) {
    const int p = blockIdx.x * blockDim.x + threadIdx.x;
    const uint64_t pol = evict_last_policy();

    float v[32];
#pragma unroll
    for (int c = 0; c < 32; c++) v[c] = __ldcs(in + (size_t)c * GHW + p);

    uint4* __restrict__ outv = (uint4*)(g_params_h + (size_t)p * GC);
#pragma unroll
    for (int q = 0; q < 4; q++) {
        union { __half2 h2[4]; uint4 u; } pack;
#pragma unroll
        for (int j = 0; j < 4; j++)
            pack.h2[j] = __floats2half2_rn(v[q * 8 + 2 * j], v[q * 8 + 2 * j + 1]);
        st16_evict_last(outv + q, pack.u, pol);
    }
}

// 16B global->shared async copy, L1-bypass (cg), evict_last L2 policy.
__device__ __forceinline__ void cp16(uint32_t dst_smem, const void* src, uint64_t pol) {
    asm volatile("cp.async.cg.shared.global.L2::cache_hint [%0], [%1], 16, %2;"
                 :: "r"(dst_smem), "l"(src), "l"(pol) : "memory");
}

// ---------------------------------------------------------------------------
// Kernel 2: bilinear gather. 2 points per thread, 4 lanes per point. Corner
// fetches go through cp.async into smem: 8 x 16B in flight per thread with NO
// register cost -> ~196KB in flight per SM at 75% occupancy (vs ~108KB when
// loads are register-resident). slots[k][tid] layout: LDS.128 readback is
// 32 lanes x consecutive 16B = conflict-free.
// ---------------------------------------------------------------------------
__global__ void __launch_bounds__(256)
gather_kernel(const float* __restrict__ coord,
              float* __restrict__ out,
              int n_points) {
    __shared__ uint4 slots[8][256];

    const int tid = threadIdx.x;
    const int t   = blockIdx.x * blockDim.x + tid;
    const int g   = t >> 2;          // pair index
    const int sub = t & 3;           // channel slice (8 channels)
    const int pA  = g * 2;
    const int pB  = pA + 1;
    if (pA >= n_points) return;

    const uint64_t pol = evict_last_policy();
    const float4 cc = __ldg(((const float4*)coord) + g);  // {xA,yA,xB,yB}

    // --- point A indices/weights ---
    const float ixA = (cc.x + 1.0f) * 0.5f * (float)(GW - 1);
    const float iyA = (cc.y + 1.0f) * 0.5f * (float)(GH - 1);
    const float fxA = floorf(ixA), fyA = floorf(iyA);
    const float ax1 = ixA - fxA, ay1 = iyA - fyA;
    const float ax0 = 1.0f - ax1, ay0 = 1.0f - ay1;
    int Ax0 = (int)fxA; Ax0 = Ax0 < 0 ? 0 : (Ax0 > GW - 1 ? GW - 1 : Ax0);
    int Ay0 = (int)fyA; Ay0 = Ay0 < 0 ? 0 : (Ay0 > GH - 1 ? GH - 1 : Ay0);
    int Ax1 = Ax0 + 1;  Ax1 = Ax1 > GW - 1 ? GW - 1 : Ax1;
    int Ay1 = Ay0 + 1;  Ay1 = Ay1 > GH - 1 ? GH - 1 : Ay1;

    // --- point B indices/weights ---
    const float ixB = (cc.z + 1.0f) * 0.5f * (float)(GW - 1);
    const float iyB = (cc.w + 1.0f) * 0.5f * (float)(GH - 1);
    const float fxB = floorf(ixB), fyB = floorf(iyB);
    const float bx1 = ixB - fxB, by1 = iyB - fyB;
    const float bx0 = 1.0f - bx1, by0 = 1.0f - by1;
    int Bx0 = (int)fxB; Bx0 = Bx0 < 0 ? 0 : (Bx0 > GW - 1 ? GW - 1 : Bx0);
    int By0 = (int)fyB; By0 = By0 < 0 ? 0 : (By0 > GH - 1 ? GH - 1 : By0);
    int Bx1 = Bx0 + 1;  Bx1 = Bx1 > GW - 1 ? GW - 1 : Bx1;
    int By1 = By0 + 1;  By1 = By1 > GH - 1 ? GH - 1 : By1;

    // Issue all 8 async corner fetches (register-free in flight).
    const uint4* __restrict__ base = (const uint4*)g_params_h;
    const uint32_t s0 = (uint32_t)__cvta_generic_to_shared(&slots[0][tid]);
    cp16(s0 + 0 * 4096, base + (((size_t)Ay0 << 10) + Ax0) * 4 + sub, pol);
    cp16(s0 + 1 * 4096, base + (((size_t)Ay0 << 10) + Ax1) * 4 + sub, pol);
    cp16(s0 + 2 * 4096, base + (((size_t)Ay1 << 10) + Ax0) * 4 + sub, pol);
    cp16(s0 + 3 * 4096, base + (((size_t)Ay1 << 10) + Ax1) * 4 + sub, pol);
    cp16(s0 + 4 * 4096, base + (((size_t)By0 << 10) + Bx0) * 4 + sub, pol);
    cp16(s0 + 5 * 4096, base + (((size_t)By0 << 10) + Bx1) * 4 + sub, pol);
    cp16(s0 + 6 * 4096, base + (((size_t)By1 << 10) + Bx0) * 4 + sub, pol);
    cp16(s0 + 7 * 4096, base + (((size_t)By1 << 10) + Bx1) * 4 + sub, pol);
    asm volatile("cp.async.commit_group;" ::: "memory");

    const float wAnw = ax0 * ay0, wAne = ax1 * ay0, wAsw = ax0 * ay1, wAse = ax1 * ay1;
    const float wBnw = bx0 * by0, wBne = bx1 * by0, wBsw = bx0 * by1, wBse = bx1 * by1;

    asm volatile("cp.async.wait_group 0;" ::: "memory");

    const uint4 A_nw = slots[0][tid];
    const uint4 A_ne = slots[1][tid];
    const uint4 A_sw = slots[2][tid];
    const uint4 A_se = slots[3][tid];
    const uint4 B_nw = slots[4][tid];
    const uint4 B_ne = slots[5][tid];
    const uint4 B_sw = slots[6][tid];
    const uint4 B_se = slots[7][tid];

    float oA[8], oB[8];
#pragma unroll
    for (int h = 0; h < 4; h++) {
        {
            const float2 a = __half22float2(*(const __half2*)&(&A_nw.x)[h]);
            const float2 b = __half22float2(*(const __half2*)&(&A_ne.x)[h]);
            const float2 c = __half22float2(*(const __half2*)&(&A_sw.x)[h]);
            const float2 d = __half22float2(*(const __half2*)&(&A_se.x)[h]);
            oA[2 * h + 0] = a.x * wAnw + b.x * wAne + c.x * wAsw + d.x * wAse;
            oA[2 * h + 1] = a.y * wAnw + b.y * wAne + c.y * wAsw + d.y * wAse;
        }
        {
            const float2 a = __half22float2(*(const __half2*)&(&B_nw.x)[h]);
            const float2 b = __half22float2(*(const __half2*)&(&B_ne.x)[h]);
            const float2 c = __half22float2(*(const __half2*)&(&B_sw.x)[h]);
            const float2 d = __half22float2(*(const __half2*)&(&B_se.x)[h]);
            oB[2 * h + 0] = a.x * wBnw + b.x * wBne + c.x * wBsw + d.x * wBse;
            oB[2 * h + 1] = a.y * wBnw + b.y * wBne + c.y * wBsw + d.y * wBse;
        }
    }

    float4* __restrict__ ovA = ((float4*)out) + (size_t)pA * 8 + 2 * sub;
    __stcs(ovA + 0, make_float4(oA[0], oA[1], oA[2], oA[3]));
    __stcs(ovA + 1, make_float4(oA[4], oA[5], oA[6], oA[7]));
    if (pB < n_points) {
        float4* __restrict__ ovB = ((float4*)out) + (size_t)pB * 8 + 2 * sub;
        __stcs(ovB + 0, make_float4(oB[0], oB[1], oB[2], oB[3]));
        __stcs(ovB + 1, make_float4(oB[4], oB[5], oB[6], oB[7]));
    }
}

extern "C" void kernel_launch(void* const* d_in, const int* in_sizes, int n_in,
                              void* d_out, int out_size) {
    const float* coord;
    const float* params;
    int coord_elems;
    if (in_sizes[0] < in_sizes[1]) {
        coord = (const float*)d_in[0];
        params = (const float*)d_in[1];
        coord_elems = in_sizes[0];
    } else {
        coord = (const float*)d_in[1];
        params = (const float*)d_in[0];
        coord_elems = in_sizes[1];
    }
    const int n_points = coord_elems / 2;

    transpose_kernel<<<GHW / 256, 256>>>(params);

    const int n_pairs = (n_points + 1) / 2;
    const int total_threads = n_pairs * 4;
    const int block = 256;
    const int grid = (total_threads + block - 1) / block;
    gather_kernel<<<grid, block>>>(coord, (float*)d_out, n_points);
}